// round 1
// baseline (speedup 1.0000x reference)
#include <cuda_runtime.h>
#include <math.h>

// ---------------------------------------------------------------------------
// Problem: x[4,2048,512] fp32, W_qkv[512,1536] fp32
//   qkv = x @ W ; split into Q,K,V [b,h=8,n=2048,d=64]
//   out[b,n,h*d] = softmax(QK^T / 8) V
// ---------------------------------------------------------------------------

#define BATCH 4
#define SEQ   2048
#define DMODEL 512
#define HEADS 8
#define DHEAD 64
#define NQKV  1536            // 3*HEADS*DHEAD
#define ROWS  (BATCH*SEQ)     // 8192

// Scratch Q/K/V in [bh][n][d] layout (16 MB each, static device BSS — no alloc)
__device__ float g_Q[BATCH*HEADS*SEQ*DHEAD];
__device__ float g_K[BATCH*HEADS*SEQ*DHEAD];
__device__ float g_V[BATCH*HEADS*SEQ*DHEAD];

// ---------------------------------------------------------------------------
// Kernel 1: QKV GEMM  C[8192,1536] = X[8192,512] @ W[512,1536]
// 128x128 block tile, TK=16, 256 threads, 8x8 micro-tile.
// Epilogue remaps each column block into g_Q/g_K/g_V with [bh][n][d] layout.
// ---------------------------------------------------------------------------
__global__ __launch_bounds__(256) void qkv_gemm_kernel(
    const float* __restrict__ X, const float* __restrict__ W)
{
    __shared__ float As[16][132];   // transposed A tile [k][m], padded
    __shared__ float Bs[16][128];   // B tile [k][n]

    const int m0 = blockIdx.y * 128;
    const int n0 = blockIdx.x * 128;
    const int tid = threadIdx.x;
    const int tx = tid & 15;        // n dim
    const int ty = tid >> 4;        // m dim

    float acc[8][8];
#pragma unroll
    for (int i = 0; i < 8; i++)
#pragma unroll
        for (int j = 0; j < 8; j++) acc[i][j] = 0.f;

    for (int k0 = 0; k0 < DMODEL; k0 += 16) {
        // Load A tile: 128 rows x 16 k  (512 float4 loads)
#pragma unroll
        for (int it = 0; it < 2; it++) {
            int idx = tid + it * 256;          // 0..511
            int row = idx >> 2;                // 0..127
            int k4  = (idx & 3) * 4;           // 0,4,8,12
            float4 a = *(const float4*)(X + (size_t)(m0 + row) * DMODEL + k0 + k4);
            As[k4 + 0][row] = a.x;
            As[k4 + 1][row] = a.y;
            As[k4 + 2][row] = a.z;
            As[k4 + 3][row] = a.w;
        }
        // Load B tile: 16 k x 128 n
#pragma unroll
        for (int it = 0; it < 2; it++) {
            int idx = tid + it * 256;
            int k  = idx >> 5;                 // 0..15
            int n4 = (idx & 31) * 4;
            *(float4*)&Bs[k][n4] =
                *(const float4*)(W + (size_t)(k0 + k) * NQKV + n0 + n4);
        }
        __syncthreads();

#pragma unroll
        for (int k = 0; k < 16; k++) {
            float4 a0 = *(float4*)&As[k][ty * 8];
            float4 a1 = *(float4*)&As[k][ty * 8 + 4];
            float4 b0 = *(float4*)&Bs[k][tx * 8];
            float4 b1 = *(float4*)&Bs[k][tx * 8 + 4];
            float av[8] = {a0.x, a0.y, a0.z, a0.w, a1.x, a1.y, a1.z, a1.w};
            float bv[8] = {b0.x, b0.y, b0.z, b0.w, b1.x, b1.y, b1.z, b1.w};
#pragma unroll
            for (int i = 0; i < 8; i++)
#pragma unroll
                for (int j = 0; j < 8; j++)
                    acc[i][j] += av[i] * bv[j];
        }
        __syncthreads();
    }

    // Epilogue: remap columns -> Q/K/V [bh][n][d].
    // 8 consecutive columns never cross a 64-boundary (tx*8 aligned), so all
    // 8 j's share (part, h) and d is consecutive -> two float4 stores per row.
    const int c0 = n0 + tx * 8;
    const int part = c0 >> 9;            // 0=Q 1=K 2=V
    const int h  = (c0 >> 6) & 7;
    const int d0 = c0 & 63;
    float* base = (part == 0) ? g_Q : (part == 1) ? g_K : g_V;

#pragma unroll
    for (int i = 0; i < 8; i++) {
        int m = m0 + ty * 8 + i;
        int b = m >> 11;                 // /2048
        int n = m & 2047;
        float* dst = base + (((size_t)(b * HEADS + h) * SEQ + n) * DHEAD + d0);
        *(float4*)(dst)     = make_float4(acc[i][0], acc[i][1], acc[i][2], acc[i][3]);
        *(float4*)(dst + 4) = make_float4(acc[i][4], acc[i][5], acc[i][6], acc[i][7]);
    }
}

// ---------------------------------------------------------------------------
// Kernel 2: flash attention.
// Grid (32 q-tiles, 32 bh). 256 threads as 16(ty=q)x16(tx=d/k), 4x4 micro.
// BQ=64, BK=64, online softmax. All fp32.
// ---------------------------------------------------------------------------
#define BQ 64
#define BK 64
#define KT_W 65   // padded row width for transposed K and for P
#define ATTN_SMEM_FLOATS (BQ*DHEAD + DHEAD*KT_W + BQ*KT_W + BK*DHEAD + 3*BQ)
#define ATTN_SMEM_BYTES  (ATTN_SMEM_FLOATS * 4)

__global__ __launch_bounds__(256) void attn_kernel(float* __restrict__ out)
{
    extern __shared__ float sm[];
    float* Qs   = sm;                       // [BQ][64]
    float* Kt   = Qs + BQ * DHEAD;          // [64][KT_W]   K transposed [d][k]
    float* Ps   = Kt + DHEAD * KT_W;        // [BQ][KT_W]   scores / probs
    float* Vs   = Ps + BQ * KT_W;           // [BK][64]
    float* m_sm = Vs + BK * DHEAD;          // [BQ]
    float* l_sm = m_sm + BQ;                // [BQ]
    float* c_sm = l_sm + BQ;                // [BQ]

    const int bh = blockIdx.y;              // 0..31
    const int qt = blockIdx.x;              // 0..31
    const int b  = bh >> 3;
    const int h  = bh & 7;
    const int tid = threadIdx.x;
    const int tx = tid & 15;
    const int ty = tid >> 4;
    const float scale = 0.125f;             // 64^-0.5

    const float* Qg = g_Q + ((size_t)bh * SEQ + qt * BQ) * DHEAD;
    const float* Kg = g_K + (size_t)bh * SEQ * DHEAD;
    const float* Vg = g_V + (size_t)bh * SEQ * DHEAD;

    // Load Q tile (row-major, coalesced)
#pragma unroll
    for (int it = 0; it < 4; it++) {
        int idx4 = tid + it * 256;          // 0..1023
        int r  = idx4 >> 4;
        int d0 = (idx4 & 15) * 4;
        *(float4*)&Qs[r * DHEAD + d0] = *(const float4*)(Qg + r * DHEAD + d0);
    }
    if (tid < BQ) { m_sm[tid] = -1e30f; l_sm[tid] = 0.f; }

    float o[4][4];
#pragma unroll
    for (int i = 0; i < 4; i++)
#pragma unroll
        for (int j = 0; j < 4; j++) o[i][j] = 0.f;

    __syncthreads();

    for (int kt = 0; kt < SEQ / BK; kt++) {
        const float* Kgt = Kg + (size_t)kt * BK * DHEAD;
        const float* Vgt = Vg + (size_t)kt * BK * DHEAD;

        // Load K (transposed into Kt[d][k]) and V (direct)
#pragma unroll
        for (int it = 0; it < 4; it++) {
            int idx4 = tid + it * 256;
            int k  = idx4 >> 4;
            int d0 = (idx4 & 15) * 4;
            float4 kk = *(const float4*)(Kgt + k * DHEAD + d0);
            Kt[(d0 + 0) * KT_W + k] = kk.x;
            Kt[(d0 + 1) * KT_W + k] = kk.y;
            Kt[(d0 + 2) * KT_W + k] = kk.z;
            Kt[(d0 + 3) * KT_W + k] = kk.w;
            *(float4*)&Vs[k * DHEAD + d0] = *(const float4*)(Vgt + k * DHEAD + d0);
        }
        __syncthreads();

        // S = Qs @ Kt : 4x4 per thread
        float s[4][4];
#pragma unroll
        for (int i = 0; i < 4; i++)
#pragma unroll
            for (int j = 0; j < 4; j++) s[i][j] = 0.f;

#pragma unroll 8
        for (int d = 0; d < DHEAD; d++) {
            float qv[4], kv[4];
#pragma unroll
            for (int i = 0; i < 4; i++) qv[i] = Qs[(ty * 4 + i) * DHEAD + d];
#pragma unroll
            for (int j = 0; j < 4; j++) kv[j] = Kt[d * KT_W + tx * 4 + j];
#pragma unroll
            for (int i = 0; i < 4; i++)
#pragma unroll
                for (int j = 0; j < 4; j++)
                    s[i][j] += qv[i] * kv[j];
        }

        // Write scaled scores to Ps
#pragma unroll
        for (int i = 0; i < 4; i++)
#pragma unroll
            for (int j = 0; j < 4; j++)
                Ps[(ty * 4 + i) * KT_W + tx * 4 + j] = s[i][j] * scale;
        __syncthreads();

        // Online softmax: one row per thread (threads 0..63)
        if (tid < BQ) {
            const int r = tid;
            float mo = m_sm[r];
            float tm = mo;
#pragma unroll 8
            for (int c = 0; c < BK; c++) tm = fmaxf(tm, Ps[r * KT_W + c]);
            float corr = __expf(mo - tm);
            float ls = 0.f;
#pragma unroll 8
            for (int c = 0; c < BK; c++) {
                float p = __expf(Ps[r * KT_W + c] - tm);
                Ps[r * KT_W + c] = p;
                ls += p;
            }
            m_sm[r] = tm;
            l_sm[r] = l_sm[r] * corr + ls;
            c_sm[r] = corr;
        }
        __syncthreads();

        // Rescale accumulators
        float cr[4];
#pragma unroll
        for (int i = 0; i < 4; i++) cr[i] = c_sm[ty * 4 + i];
#pragma unroll
        for (int i = 0; i < 4; i++)
#pragma unroll
            for (int j = 0; j < 4; j++) o[i][j] *= cr[i];

        // O += P @ V : 4x4 per thread
#pragma unroll 8
        for (int k = 0; k < BK; k++) {
            float pv[4];
#pragma unroll
            for (int i = 0; i < 4; i++) pv[i] = Ps[(ty * 4 + i) * KT_W + k];
            float4 vv = *(float4*)&Vs[k * DHEAD + tx * 4];
            float vj[4] = {vv.x, vv.y, vv.z, vv.w};
#pragma unroll
            for (int i = 0; i < 4; i++)
#pragma unroll
                for (int j = 0; j < 4; j++)
                    o[i][j] += pv[i] * vj[j];
        }
        __syncthreads();
    }

    // Finalize and write: out[b][q][h*64 + d]
#pragma unroll
    for (int i = 0; i < 4; i++) {
        float linv = 1.f / l_sm[ty * 4 + i];
        int q = qt * BQ + ty * 4 + i;
        float4 r4 = make_float4(o[i][0] * linv, o[i][1] * linv,
                                o[i][2] * linv, o[i][3] * linv);
        *(float4*)(out + ((size_t)b * SEQ + q) * DMODEL + h * DHEAD + tx * 4) = r4;
    }
}

// ---------------------------------------------------------------------------
extern "C" void kernel_launch(void* const* d_in, const int* in_sizes, int n_in,
                              void* d_out, int out_size)
{
    (void)in_sizes; (void)n_in; (void)out_size;
    const float* x = (const float*)d_in[0];
    const float* w = (const float*)d_in[1];
    float* out = (float*)d_out;

    cudaFuncSetAttribute(attn_kernel,
                         cudaFuncAttributeMaxDynamicSharedMemorySize,
                         ATTN_SMEM_BYTES);

    qkv_gemm_kernel<<<dim3(NQKV / 128, ROWS / 128), 256>>>(x, w);
    attn_kernel<<<dim3(SEQ / BQ, BATCH * HEADS), 256, ATTN_SMEM_BYTES>>>(out);
}